// round 1
// baseline (speedup 1.0000x reference)
#include <cuda_runtime.h>
#include <cstdint>
#include <math.h>

#define S_TOK 4096
#define HID   1024
#define FF    4096
#define NE    8
#define CAP   1280
#define TWOF  8192

// ---------------- scratch (__device__ globals; no allocations allowed) ----------------
__device__ int   g_e1[S_TOK], g_e2[S_TOK];
__device__ float g_p1[S_TOK], g_p2[S_TOK];
__device__ int   g_slot1[S_TOK], g_slot2[S_TOK];
__device__ float g_fw1[S_TOK], g_fw2[S_TOK];
__device__ int   g_slot_token[NE * CAP];

__device__ float g_G  [(size_t)NE * CAP * TWOF];  // [E*C, 2F]
__device__ float g_U  [(size_t)NE * CAP * FF];    // [E*C, F]
__device__ float g_ACT[(size_t)NE * CAP * FF];    // [E*C, F]
__device__ float g_EOUT[(size_t)NE * CAP * HID];  // [E*C, H]

// ---------------- helpers ----------------
__device__ __forceinline__ float f2tf32(float x) {
    uint32_t u;
    asm("cvt.rna.tf32.f32 %0, %1;" : "=r"(u) : "f"(x));
    return __uint_as_float(u);
}

__device__ __forceinline__ void mma_tf32(float* d, const uint32_t* a, const uint32_t* b) {
    asm("mma.sync.aligned.m16n8k8.row.col.f32.tf32.tf32.f32 "
        "{%0,%1,%2,%3}, {%4,%5,%6,%7}, {%8,%9}, {%0,%1,%2,%3};"
        : "+f"(d[0]), "+f"(d[1]), "+f"(d[2]), "+f"(d[3])
        : "r"(a[0]), "r"(a[1]), "r"(a[2]), "r"(a[3]), "r"(b[0]), "r"(b[1]));
}

// ---------------- 1) router: logits, softmax, top-2 ----------------
__global__ void __launch_bounds__(256) router_kernel(const float* __restrict__ hid,
                                                     const float* __restrict__ gw) {
    int s = blockIdx.x;
    int tid = threadIdx.x;
    __shared__ float red[NE][256];
    float acc[NE];
#pragma unroll
    for (int e = 0; e < NE; e++) acc[e] = 0.f;
    const float* row = hid + (size_t)s * HID;
#pragma unroll
    for (int it = 0; it < HID / 256; it++) {
        int h = tid + it * 256;
        float x = row[h];
        float4 glo = *(const float4*)(gw + (size_t)h * NE);
        float4 ghi = *(const float4*)(gw + (size_t)h * NE + 4);
        acc[0] += x * glo.x; acc[1] += x * glo.y; acc[2] += x * glo.z; acc[3] += x * glo.w;
        acc[4] += x * ghi.x; acc[5] += x * ghi.y; acc[6] += x * ghi.z; acc[7] += x * ghi.w;
    }
#pragma unroll
    for (int e = 0; e < NE; e++) red[e][tid] = acc[e];
    __syncthreads();
    for (int st = 128; st > 0; st >>= 1) {
        if (tid < st) {
#pragma unroll
            for (int e = 0; e < NE; e++) red[e][tid] += red[e][tid + st];
        }
        __syncthreads();
    }
    if (tid == 0) {
        float l[NE];
#pragma unroll
        for (int e = 0; e < NE; e++) l[e] = red[e][0];
        float m = l[0];
#pragma unroll
        for (int e = 1; e < NE; e++) m = fmaxf(m, l[e]);
        float p[NE]; float se = 0.f;
#pragma unroll
        for (int e = 0; e < NE; e++) { p[e] = expf(l[e] - m); se += p[e]; }
        float inv = 1.f / se;
#pragma unroll
        for (int e = 0; e < NE; e++) p[e] *= inv;
        int t1 = 0; float b1 = p[0];
        for (int e = 1; e < NE; e++) if (p[e] > b1) { b1 = p[e]; t1 = e; }
        int t2 = (t1 == 0) ? 1 : 0; float b2 = p[t2];
        for (int e = 0; e < NE; e++) if (e != t1 && p[e] > b2) { b2 = p[e]; t2 = e; }
        g_e1[s] = t1; g_e2[s] = t2; g_p1[s] = b1; g_p2[s] = b2;
    }
}

// ---------------- 2) scan: ranks + capacity + slot map (single block) ----------------
__global__ void __launch_bounds__(256) scan_kernel() {
    __shared__ unsigned char se1[S_TOK], se2[S_TOK];
    __shared__ int c1[256][NE], c2[256][NE];
    int tid = threadIdx.x;
    for (int i = tid; i < NE * CAP; i += 256) g_slot_token[i] = -1;
    for (int i = tid; i < S_TOK; i += 256) {
        se1[i] = (unsigned char)g_e1[i];
        se2[i] = (unsigned char)g_e2[i];
    }
    __syncthreads();
    int lc1[NE], lc2[NE];
#pragma unroll
    for (int e = 0; e < NE; e++) { lc1[e] = 0; lc2[e] = 0; }
    for (int j = 0; j < 16; j++) {
        int s = tid * 16 + j;
        lc1[se1[s]]++;
        lc2[se2[s]]++;
    }
#pragma unroll
    for (int e = 0; e < NE; e++) { c1[tid][e] = lc1[e]; c2[tid][e] = lc2[e]; }
    __syncthreads();
    if (tid < NE) {
        int e = tid;
        int run = 0;
        for (int t = 0; t < 256; t++) { int v = c1[t][e]; c1[t][e] = run; run += v; }
        int run2 = run;  // rank2 base = PRE-capacity top1 total (matches reference)
        for (int t = 0; t < 256; t++) { int v = c2[t][e]; c2[t][e] = run2; run2 += v; }
    }
    __syncthreads();
    int o1[NE], o2[NE];
#pragma unroll
    for (int e = 0; e < NE; e++) { o1[e] = c1[tid][e]; o2[e] = c2[tid][e]; }
    for (int j = 0; j < 16; j++) {
        int s = tid * 16 + j;
        int e1 = se1[s], e2 = se2[s];
        int r1 = o1[e1]++;
        int r2 = o2[e2]++;
        if (r1 < CAP) {
            int sl = e1 * CAP + r1;
            g_slot1[s] = sl; g_slot_token[sl] = s; g_fw1[s] = g_p1[s];
        } else { g_slot1[s] = 0; g_fw1[s] = 0.f; }
        if (r2 < CAP) {
            int sl = e2 * CAP + r2;
            g_slot2[s] = sl; g_slot_token[sl] = s; g_fw2[s] = g_p2[s];
        } else { g_slot2[s] = 0; g_fw2[s] = 0.f; }
    }
}

// ---------------- shared GEMM tile compute (tf32 mma.sync, 128x128x32) ----------------
// As stride 36 (36%32==4): frag addr = 4*row+col -> 32 distinct banks across the warp.
// Bs stride 136 (136%32==8): frag addr = 8*k+n   -> 32 distinct banks across the warp.
__device__ __forceinline__ void tile_compute(const float (*As)[36], const float (*Bs)[136],
                                             float (*acc)[8][4],
                                             int warp_m, int warp_n, int g, int c) {
#pragma unroll
    for (int k0 = 0; k0 < 32; k0 += 8) {
        uint32_t a[2][4];
        uint32_t b[8][2];
#pragma unroll
        for (int mt = 0; mt < 2; mt++) {
            int r0 = warp_m * 32 + mt * 16;
            a[mt][0] = __float_as_uint(As[r0 + g][k0 + c]);
            a[mt][1] = __float_as_uint(As[r0 + g + 8][k0 + c]);
            a[mt][2] = __float_as_uint(As[r0 + g][k0 + c + 4]);
            a[mt][3] = __float_as_uint(As[r0 + g + 8][k0 + c + 4]);
        }
#pragma unroll
        for (int nt = 0; nt < 8; nt++) {
            int col = warp_n * 64 + nt * 8 + g;
            b[nt][0] = __float_as_uint(Bs[k0 + c][col]);
            b[nt][1] = __float_as_uint(Bs[k0 + c + 4][col]);
        }
#pragma unroll
        for (int mt = 0; mt < 2; mt++)
#pragma unroll
            for (int nt = 0; nt < 8; nt++)
                mma_tf32(acc[mt][nt], a[mt], b[nt]);
    }
}

// ---------------- 3) GEMM1: gathered tokens x {w_gate|w_up} -> G, U ----------------
// grid: (m_tiles=10, n_tiles=96 over 3F, experts=8)
__global__ void __launch_bounds__(256, 1) gemm1_kernel(const float* __restrict__ tokens,
                                                       const float* __restrict__ w_gate,
                                                       const float* __restrict__ w_up) {
    int e  = blockIdx.z;
    int m0 = blockIdx.x * 128;
    int n0 = blockIdx.y * 128;

    __shared__ float As[128][36];
    __shared__ float Bs[32][136];
    __shared__ int stok[128];

    int tid = threadIdx.x;
    const float* B; int ldb; float* Cout; int ldc;
    if (n0 < TWOF) {
        B = w_gate + (size_t)e * HID * TWOF + n0; ldb = TWOF;
        Cout = g_G + (size_t)e * CAP * TWOF + n0; ldc = TWOF;
    } else {
        B = w_up + (size_t)e * HID * FF + (n0 - TWOF); ldb = FF;
        Cout = g_U + (size_t)e * CAP * FF + (n0 - TWOF); ldc = FF;
    }
    for (int i = tid; i < 128; i += 256) stok[i] = g_slot_token[e * CAP + m0 + i];
    __syncthreads();

    float acc[2][8][4];
#pragma unroll
    for (int mt = 0; mt < 2; mt++)
#pragma unroll
        for (int nt = 0; nt < 8; nt++)
#pragma unroll
            for (int i = 0; i < 4; i++) acc[mt][nt][i] = 0.f;

    int warp = tid >> 5, lane = tid & 31;
    int warp_m = warp >> 1, warp_n = warp & 1;
    int g = lane >> 2, c = lane & 3;

    for (int kt = 0; kt < HID; kt += 32) {
        // A tile: 128 x 32 (gather by slot)
#pragma unroll
        for (int i = 0; i < 4; i++) {
            int id = tid + i * 256;
            int r = id >> 3, c4 = (id & 7) << 2;
            int tok = stok[r];
            float4 v = make_float4(0.f, 0.f, 0.f, 0.f);
            if (tok >= 0) v = *(const float4*)(tokens + (size_t)tok * HID + kt + c4);
            As[r][c4 + 0] = f2tf32(v.x);
            As[r][c4 + 1] = f2tf32(v.y);
            As[r][c4 + 2] = f2tf32(v.z);
            As[r][c4 + 3] = f2tf32(v.w);
        }
        // B tile: 32 x 128
#pragma unroll
        for (int i = 0; i < 4; i++) {
            int id = tid + i * 256;
            int r = id >> 5, c4 = (id & 31) << 2;
            float4 v = *(const float4*)(B + (size_t)(kt + r) * ldb + c4);
            Bs[r][c4 + 0] = f2tf32(v.x);
            Bs[r][c4 + 1] = f2tf32(v.y);
            Bs[r][c4 + 2] = f2tf32(v.z);
            Bs[r][c4 + 3] = f2tf32(v.w);
        }
        __syncthreads();
        tile_compute(As, Bs, acc, warp_m, warp_n, g, c);
        __syncthreads();
    }

#pragma unroll
    for (int mt = 0; mt < 2; mt++)
#pragma unroll
        for (int nt = 0; nt < 8; nt++) {
            int row = m0 + warp_m * 32 + mt * 16 + g;
            int col = warp_n * 64 + nt * 8 + c * 2;
            *(float2*)(Cout + (size_t)row * ldc + col)       = make_float2(acc[mt][nt][0], acc[mt][nt][1]);
            *(float2*)(Cout + (size_t)(row + 8) * ldc + col) = make_float2(acc[mt][nt][2], acc[mt][nt][3]);
        }
}

// ---------------- 4) SwiGLU: ACT = x1 * silu(x2) * u ----------------
__global__ void __launch_bounds__(256) act_kernel() {
    size_t i4  = (size_t)blockIdx.x * 256 + threadIdx.x;
    size_t idx = i4 * 4;                       // element index into [E*C, F]
    size_t row = idx >> 12;                    // / FF
    int f = (int)(idx & (FF - 1));
    float4 x1 = *(const float4*)(g_G + row * TWOF + f);
    float4 x2 = *(const float4*)(g_G + row * TWOF + FF + f);
    float4 u  = *(const float4*)(g_U + idx);
    float4 o;
    o.x = x1.x * (x2.x / (1.f + __expf(-x2.x))) * u.x;
    o.y = x1.y * (x2.y / (1.f + __expf(-x2.y))) * u.y;
    o.z = x1.z * (x2.z / (1.f + __expf(-x2.z))) * u.z;
    o.w = x1.w * (x2.w / (1.f + __expf(-x2.w))) * u.w;
    *(float4*)(g_ACT + idx) = o;
}

// ---------------- 5) GEMM2: ACT x w_down -> EOUT ----------------
// grid: (m_tiles=10, n_tiles=8 over H, experts=8)
__global__ void __launch_bounds__(256, 1) gemm2_kernel(const float* __restrict__ w_down) {
    int e  = blockIdx.z;
    int m0 = blockIdx.x * 128;
    int n0 = blockIdx.y * 128;

    __shared__ float As[128][36];
    __shared__ float Bs[32][136];

    int tid = threadIdx.x;
    const float* A = g_ACT + (size_t)(e * CAP + m0) * FF;
    const float* B = w_down + (size_t)e * FF * HID + n0;
    float* Cout = g_EOUT + (size_t)e * CAP * HID + n0;

    float acc[2][8][4];
#pragma unroll
    for (int mt = 0; mt < 2; mt++)
#pragma unroll
        for (int nt = 0; nt < 8; nt++)
#pragma unroll
            for (int i = 0; i < 4; i++) acc[mt][nt][i] = 0.f;

    int warp = tid >> 5, lane = tid & 31;
    int warp_m = warp >> 1, warp_n = warp & 1;
    int g = lane >> 2, c = lane & 3;

    for (int kt = 0; kt < FF; kt += 32) {
#pragma unroll
        for (int i = 0; i < 4; i++) {
            int id = tid + i * 256;
            int r = id >> 3, c4 = (id & 7) << 2;
            float4 v = *(const float4*)(A + (size_t)r * FF + kt + c4);
            As[r][c4 + 0] = f2tf32(v.x);
            As[r][c4 + 1] = f2tf32(v.y);
            As[r][c4 + 2] = f2tf32(v.z);
            As[r][c4 + 3] = f2tf32(v.w);
        }
#pragma unroll
        for (int i = 0; i < 4; i++) {
            int id = tid + i * 256;
            int r = id >> 5, c4 = (id & 31) << 2;
            float4 v = *(const float4*)(B + (size_t)(kt + r) * HID + c4);
            Bs[r][c4 + 0] = f2tf32(v.x);
            Bs[r][c4 + 1] = f2tf32(v.y);
            Bs[r][c4 + 2] = f2tf32(v.z);
            Bs[r][c4 + 3] = f2tf32(v.w);
        }
        __syncthreads();
        tile_compute(As, Bs, acc, warp_m, warp_n, g, c);
        __syncthreads();
    }

#pragma unroll
    for (int mt = 0; mt < 2; mt++)
#pragma unroll
        for (int nt = 0; nt < 8; nt++) {
            int row = m0 + warp_m * 32 + mt * 16 + g;
            int col = warp_n * 64 + nt * 8 + c * 2;
            *(float2*)(Cout + (size_t)row * HID + col)       = make_float2(acc[mt][nt][0], acc[mt][nt][1]);
            *(float2*)(Cout + (size_t)(row + 8) * HID + col) = make_float2(acc[mt][nt][2], acc[mt][nt][3]);
        }
}

// ---------------- 6) combine ----------------
__global__ void __launch_bounds__(256) combine_kernel(float* __restrict__ out) {
    int s = blockIdx.x;
    int h = threadIdx.x * 4;
    int sl1 = g_slot1[s], sl2 = g_slot2[s];
    float w1 = g_fw1[s], w2 = g_fw2[s];
    float4 a = *(const float4*)(g_EOUT + (size_t)sl1 * HID + h);
    float4 b = *(const float4*)(g_EOUT + (size_t)sl2 * HID + h);
    float4 o;
    o.x = w1 * a.x + w2 * b.x;
    o.y = w1 * a.y + w2 * b.y;
    o.z = w1 * a.z + w2 * b.z;
    o.w = w1 * a.w + w2 * b.w;
    *(float4*)(out + (size_t)s * HID + h) = o;
}

// ---------------- launch ----------------
extern "C" void kernel_launch(void* const* d_in, const int* in_sizes, int n_in,
                              void* d_out, int out_size) {
    const float* hid = (const float*)d_in[0];
    const float* gw  = (const float*)d_in[1];
    const float* wg  = (const float*)d_in[2];
    const float* wu  = (const float*)d_in[3];
    const float* wd  = (const float*)d_in[4];
    float* out = (float*)d_out;

    router_kernel<<<S_TOK, 256>>>(hid, gw);
    scan_kernel<<<1, 256>>>();
    gemm1_kernel<<<dim3(10, 96, 8), 256>>>(hid, wg, wu);
    act_kernel<<<(NE * CAP * FF) / (256 * 4), 256>>>();
    gemm2_kernel<<<dim3(10, 8, 8), 256>>>(wd);
    combine_kernel<<<S_TOK, 256>>>(out);
}

// round 2
// speedup vs baseline: 1.6475x; 1.6475x over previous
#include <cuda_runtime.h>
#include <cstdint>
#include <math.h>

#define S_TOK 4096
#define HID   1024
#define FF    4096
#define NE    8
#define CAP   1280
#define TWOF  8192

// ---------------- scratch (__device__ globals; no allocations allowed) ----------------
__device__ int   g_e1[S_TOK], g_e2[S_TOK];
__device__ float g_p1[S_TOK], g_p2[S_TOK];
__device__ int   g_slot1[S_TOK], g_slot2[S_TOK];
__device__ float g_fw1[S_TOK], g_fw2[S_TOK];
__device__ int   g_slot_token[NE * CAP];

__device__ float g_ACT [(size_t)NE * CAP * FF];   // [E*C, F]
__device__ float g_EOUT[(size_t)NE * CAP * HID];  // [E*C, H]

// ---------------- helpers ----------------
__device__ __forceinline__ uint32_t f2tf32u(float x) {
    uint32_t u;
    asm("cvt.rna.tf32.f32 %0, %1;" : "=r"(u) : "f"(x));
    return u;
}

__device__ __forceinline__ void mma_tf32(float* d, const uint32_t* a, const uint32_t* b) {
    asm("mma.sync.aligned.m16n8k8.row.col.f32.tf32.tf32.f32 "
        "{%0,%1,%2,%3}, {%4,%5,%6,%7}, {%8,%9}, {%0,%1,%2,%3};"
        : "+f"(d[0]), "+f"(d[1]), "+f"(d[2]), "+f"(d[3])
        : "r"(a[0]), "r"(a[1]), "r"(a[2]), "r"(a[3]), "r"(b[0]), "r"(b[1]));
}

__device__ __forceinline__ void cp16(uint32_t saddr, const void* gaddr, bool valid) {
    int sz = valid ? 16 : 0;
    asm volatile("cp.async.cg.shared.global [%0], [%1], 16, %2;\n"
                 :: "r"(saddr), "l"(gaddr), "r"(sz));
}
#define CP_COMMIT() asm volatile("cp.async.commit_group;\n" ::: "memory")
#define CP_WAIT0()  asm volatile("cp.async.wait_group 0;\n" ::: "memory")

// ---------------- 1) router: logits, softmax, top-2 ----------------
__global__ void __launch_bounds__(256) router_kernel(const float* __restrict__ hid,
                                                     const float* __restrict__ gw) {
    int s = blockIdx.x;
    int tid = threadIdx.x;
    __shared__ float red[NE][256];
    float acc[NE];
#pragma unroll
    for (int e = 0; e < NE; e++) acc[e] = 0.f;
    const float* row = hid + (size_t)s * HID;
#pragma unroll
    for (int it = 0; it < HID / 256; it++) {
        int h = tid + it * 256;
        float x = row[h];
        float4 glo = *(const float4*)(gw + (size_t)h * NE);
        float4 ghi = *(const float4*)(gw + (size_t)h * NE + 4);
        acc[0] += x * glo.x; acc[1] += x * glo.y; acc[2] += x * glo.z; acc[3] += x * glo.w;
        acc[4] += x * ghi.x; acc[5] += x * ghi.y; acc[6] += x * ghi.z; acc[7] += x * ghi.w;
    }
#pragma unroll
    for (int e = 0; e < NE; e++) red[e][tid] = acc[e];
    __syncthreads();
    for (int st = 128; st > 0; st >>= 1) {
        if (tid < st) {
#pragma unroll
            for (int e = 0; e < NE; e++) red[e][tid] += red[e][tid + st];
        }
        __syncthreads();
    }
    if (tid == 0) {
        float l[NE];
#pragma unroll
        for (int e = 0; e < NE; e++) l[e] = red[e][0];
        float m = l[0];
#pragma unroll
        for (int e = 1; e < NE; e++) m = fmaxf(m, l[e]);
        float p[NE]; float se = 0.f;
#pragma unroll
        for (int e = 0; e < NE; e++) { p[e] = expf(l[e] - m); se += p[e]; }
        float inv = 1.f / se;
#pragma unroll
        for (int e = 0; e < NE; e++) p[e] *= inv;
        int t1 = 0; float b1 = p[0];
        for (int e = 1; e < NE; e++) if (p[e] > b1) { b1 = p[e]; t1 = e; }
        int t2 = (t1 == 0) ? 1 : 0; float b2 = p[t2];
        for (int e = 0; e < NE; e++) if (e != t1 && p[e] > b2) { b2 = p[e]; t2 = e; }
        g_e1[s] = t1; g_e2[s] = t2; g_p1[s] = b1; g_p2[s] = b2;
    }
}

// ---------------- 2) scan: ranks + capacity + slot map (single block) ----------------
__global__ void __launch_bounds__(256) scan_kernel() {
    __shared__ unsigned char se1[S_TOK], se2[S_TOK];
    __shared__ int c1[256][NE], c2[256][NE];
    int tid = threadIdx.x;
    for (int i = tid; i < NE * CAP; i += 256) g_slot_token[i] = -1;
    for (int i = tid; i < S_TOK; i += 256) {
        se1[i] = (unsigned char)g_e1[i];
        se2[i] = (unsigned char)g_e2[i];
    }
    __syncthreads();
    int lc1[NE], lc2[NE];
#pragma unroll
    for (int e = 0; e < NE; e++) { lc1[e] = 0; lc2[e] = 0; }
    for (int j = 0; j < 16; j++) {
        int s = tid * 16 + j;
        lc1[se1[s]]++;
        lc2[se2[s]]++;
    }
#pragma unroll
    for (int e = 0; e < NE; e++) { c1[tid][e] = lc1[e]; c2[tid][e] = lc2[e]; }
    __syncthreads();
    if (tid < NE) {
        int e = tid;
        int run = 0;
        for (int t = 0; t < 256; t++) { int v = c1[t][e]; c1[t][e] = run; run += v; }
        int run2 = run;  // rank2 base = PRE-capacity top1 total (matches reference)
        for (int t = 0; t < 256; t++) { int v = c2[t][e]; c2[t][e] = run2; run2 += v; }
    }
    __syncthreads();
    int o1[NE], o2[NE];
#pragma unroll
    for (int e = 0; e < NE; e++) { o1[e] = c1[tid][e]; o2[e] = c2[tid][e]; }
    for (int j = 0; j < 16; j++) {
        int s = tid * 16 + j;
        int e1 = se1[s], e2 = se2[s];
        int r1 = o1[e1]++;
        int r2 = o2[e2]++;
        if (r1 < CAP) {
            int sl = e1 * CAP + r1;
            g_slot1[s] = sl; g_slot_token[sl] = s; g_fw1[s] = g_p1[s];
        } else { g_slot1[s] = 0; g_fw1[s] = 0.f; }
        if (r2 < CAP) {
            int sl = e2 * CAP + r2;
            g_slot2[s] = sl; g_slot_token[sl] = s; g_fw2[s] = g_p2[s];
        } else { g_slot2[s] = 0; g_fw2[s] = 0.f; }
    }
}

// ================= 3) fused GEMM1 + SwiGLU =================
// Block computes a 128(row) x 64(f) tile of x1, x2, u (three MMAs sharing the
// gathered A tile), applies act = x1*silu(x2)*u in registers, writes ACT only.
// 512 threads = 16 warps in a 4(m) x 4(n) grid; each warp owns 32x16 per matrix.
// Dyn smem: As[2][128][36] (+36 stride: conflict-free frag LDS),
//           Bs[2][3][32][72] (stride 72 == 8 mod 32: conflict-free frag LDS).
#define G1_A_BUF 4608   // 128*36
#define G1_B_BUF 6912   // 3*32*72
#define G1_B_MAT 2304   // 32*72
#define G1_SMEM  ((2*G1_A_BUF + 2*G1_B_BUF) * 4)

__global__ void __launch_bounds__(512, 1) gemm1_kernel(const float* __restrict__ tokens,
                                                       const float* __restrict__ w_gate,
                                                       const float* __restrict__ w_up) {
    extern __shared__ float sm[];
    float* As = sm;
    float* Bs = sm + 2 * G1_A_BUF;
    __shared__ int stok[128];

    const int e  = blockIdx.z;
    const int m0 = blockIdx.x * 128;
    const int f0 = blockIdx.y * 64;
    const int tid = threadIdx.x;

    const float* B0 = w_gate + (size_t)e * HID * TWOF + f0;        // x1
    const float* B1 = w_gate + (size_t)e * HID * TWOF + FF + f0;   // x2
    const float* B2 = w_up   + (size_t)e * HID * FF + f0;          // u

    if (tid < 128) stok[tid] = g_slot_token[e * CAP + m0 + tid];
    __syncthreads();

    const uint32_t a_sm = (uint32_t)__cvta_generic_to_shared(As);
    const uint32_t b_sm = (uint32_t)__cvta_generic_to_shared(Bs);

    // per-thread load coords
    const int ar0 = tid >> 3, ac = (tid & 7) << 2;         // A rows tid>>3 and +64
    const int br = tid >> 4, bc = (tid & 15) << 2;         // B row/col

    const int tok0 = stok[ar0];
    const int tok1 = stok[ar0 + 64];

#define G1_ISSUE(buf, kt)                                                              \
    do {                                                                               \
        cp16(a_sm + 4u * ((buf) * G1_A_BUF + ar0 * 36 + ac),                           \
             tokens + (size_t)(tok0 < 0 ? 0 : tok0) * HID + (kt) + ac, tok0 >= 0);     \
        cp16(a_sm + 4u * ((buf) * G1_A_BUF + (ar0 + 64) * 36 + ac),                    \
             tokens + (size_t)(tok1 < 0 ? 0 : tok1) * HID + (kt) + ac, tok1 >= 0);     \
        cp16(b_sm + 4u * ((buf) * G1_B_BUF + 0 * G1_B_MAT + br * 72 + bc),             \
             B0 + (size_t)((kt) + br) * TWOF + bc, true);                              \
        cp16(b_sm + 4u * ((buf) * G1_B_BUF + 1 * G1_B_MAT + br * 72 + bc),             \
             B1 + (size_t)((kt) + br) * TWOF + bc, true);                              \
        cp16(b_sm + 4u * ((buf) * G1_B_BUF + 2 * G1_B_MAT + br * 72 + bc),             \
             B2 + (size_t)((kt) + br) * FF + bc, true);                                \
        CP_COMMIT();                                                                   \
    } while (0)

    float acc[3][2][2][4];
#pragma unroll
    for (int j = 0; j < 3; j++)
#pragma unroll
        for (int mt = 0; mt < 2; mt++)
#pragma unroll
            for (int nt = 0; nt < 2; nt++)
#pragma unroll
                for (int i = 0; i < 4; i++) acc[j][mt][nt][i] = 0.f;

    const int warp = tid >> 5, lane = tid & 31;
    const int warp_m = warp >> 2, warp_n = warp & 3;
    const int g = lane >> 2, c = lane & 3;

    G1_ISSUE(0, 0);
    int buf = 0;
    for (int kt = 0; kt < HID; kt += 32, buf ^= 1) {
        CP_WAIT0();
        __syncthreads();
        if (kt + 32 < HID) G1_ISSUE(buf ^ 1, kt + 32);

        const float* Ab = As + buf * G1_A_BUF;
        const float* Bb = Bs + buf * G1_B_BUF;
#pragma unroll
        for (int k0 = 0; k0 < 32; k0 += 8) {
            uint32_t a[2][4];
#pragma unroll
            for (int mt = 0; mt < 2; mt++) {
                int r0 = warp_m * 32 + mt * 16;
                a[mt][0] = f2tf32u(Ab[(r0 + g) * 36 + k0 + c]);
                a[mt][1] = f2tf32u(Ab[(r0 + g + 8) * 36 + k0 + c]);
                a[mt][2] = f2tf32u(Ab[(r0 + g) * 36 + k0 + c + 4]);
                a[mt][3] = f2tf32u(Ab[(r0 + g + 8) * 36 + k0 + c + 4]);
            }
            uint32_t b[3][2][2];
#pragma unroll
            for (int j = 0; j < 3; j++)
#pragma unroll
                for (int nt = 0; nt < 2; nt++) {
                    int col = warp_n * 16 + nt * 8 + g;
                    b[j][nt][0] = f2tf32u(Bb[j * G1_B_MAT + (k0 + c) * 72 + col]);
                    b[j][nt][1] = f2tf32u(Bb[j * G1_B_MAT + (k0 + c + 4) * 72 + col]);
                }
#pragma unroll
            for (int j = 0; j < 3; j++)
#pragma unroll
                for (int mt = 0; mt < 2; mt++)
#pragma unroll
                    for (int nt = 0; nt < 2; nt++)
                        mma_tf32(acc[j][mt][nt], a[mt], b[j][nt]);
        }
    }

    // epilogue: act = x1 * silu(x2) * u, write ACT
#pragma unroll
    for (int mt = 0; mt < 2; mt++)
#pragma unroll
        for (int nt = 0; nt < 2; nt++) {
            int row = m0 + warp_m * 32 + mt * 16 + g;
            int col = f0 + warp_n * 16 + nt * 8 + c * 2;
            float o[4];
#pragma unroll
            for (int i = 0; i < 4; i++) {
                float x1 = acc[0][mt][nt][i];
                float x2 = acc[1][mt][nt][i];
                float u  = acc[2][mt][nt][i];
                o[i] = x1 * (x2 / (1.f + __expf(-x2))) * u;
            }
            float* d0 = g_ACT + ((size_t)(e * CAP) + row) * FF + col;
            float* d1 = g_ACT + ((size_t)(e * CAP) + row + 8) * FF + col;
            *(float2*)d0 = make_float2(o[0], o[1]);
            *(float2*)d1 = make_float2(o[2], o[3]);
        }
#undef G1_ISSUE
}

// ================= 5) GEMM2: ACT x w_down -> EOUT =================
// 128x128 tile, 512 threads = 16 warps in 4x4 grid; each warp owns 32x32.
#define G2_A_BUF 4608   // 128*36
#define G2_B_BUF 4352   // 32*136
#define G2_SMEM  ((2*G2_A_BUF + 2*G2_B_BUF) * 4)

__global__ void __launch_bounds__(512, 1) gemm2_kernel(const float* __restrict__ w_down) {
    extern __shared__ float sm[];
    float* As = sm;
    float* Bs = sm + 2 * G2_A_BUF;

    const int e  = blockIdx.z;
    const int m0 = blockIdx.x * 128;
    const int n0 = blockIdx.y * 128;
    const int tid = threadIdx.x;

    const float* A = g_ACT + (size_t)(e * CAP + m0) * FF;
    const float* B = w_down + (size_t)e * FF * HID + n0;
    float* Cout = g_EOUT + (size_t)e * CAP * HID + n0;

    const uint32_t a_sm = (uint32_t)__cvta_generic_to_shared(As);
    const uint32_t b_sm = (uint32_t)__cvta_generic_to_shared(Bs);

    const int ar0 = tid >> 3, ac = (tid & 7) << 2;     // A rows: ar0, ar0+64
    const int br0 = tid >> 5, bc = (tid & 31) << 2;    // B rows: br0, br0+16

#define G2_ISSUE(buf, kt)                                                          \
    do {                                                                           \
        cp16(a_sm + 4u * ((buf) * G2_A_BUF + ar0 * 36 + ac),                       \
             A + (size_t)ar0 * FF + (kt) + ac, true);                              \
        cp16(a_sm + 4u * ((buf) * G2_A_BUF + (ar0 + 64) * 36 + ac),                \
             A + (size_t)(ar0 + 64) * FF + (kt) + ac, true);                       \
        cp16(b_sm + 4u * ((buf) * G2_B_BUF + br0 * 136 + bc),                      \
             B + (size_t)((kt) + br0) * HID + bc, true);                           \
        cp16(b_sm + 4u * ((buf) * G2_B_BUF + (br0 + 16) * 136 + bc),               \
             B + (size_t)((kt) + br0 + 16) * HID + bc, true);                      \
        CP_COMMIT();                                                               \
    } while (0)

    float acc[2][4][4];
#pragma unroll
    for (int mt = 0; mt < 2; mt++)
#pragma unroll
        for (int nt = 0; nt < 4; nt++)
#pragma unroll
            for (int i = 0; i < 4; i++) acc[mt][nt][i] = 0.f;

    const int warp = tid >> 5, lane = tid & 31;
    const int warp_m = warp >> 2, warp_n = warp & 3;
    const int g = lane >> 2, c = lane & 3;

    G2_ISSUE(0, 0);
    int buf = 0;
    for (int kt = 0; kt < FF; kt += 32, buf ^= 1) {
        CP_WAIT0();
        __syncthreads();
        if (kt + 32 < FF) G2_ISSUE(buf ^ 1, kt + 32);

        const float* Ab = As + buf * G2_A_BUF;
        const float* Bb = Bs + buf * G2_B_BUF;
#pragma unroll
        for (int k0 = 0; k0 < 32; k0 += 8) {
            uint32_t a[2][4];
#pragma unroll
            for (int mt = 0; mt < 2; mt++) {
                int r0 = warp_m * 32 + mt * 16;
                a[mt][0] = f2tf32u(Ab[(r0 + g) * 36 + k0 + c]);
                a[mt][1] = f2tf32u(Ab[(r0 + g + 8) * 36 + k0 + c]);
                a[mt][2] = f2tf32u(Ab[(r0 + g) * 36 + k0 + c + 4]);
                a[mt][3] = f2tf32u(Ab[(r0 + g + 8) * 36 + k0 + c + 4]);
            }
            uint32_t b[4][2];
#pragma unroll
            for (int nt = 0; nt < 4; nt++) {
                int col = warp_n * 32 + nt * 8 + g;
                b[nt][0] = f2tf32u(Bb[(k0 + c) * 136 + col]);
                b[nt][1] = f2tf32u(Bb[(k0 + c + 4) * 136 + col]);
            }
#pragma unroll
            for (int mt = 0; mt < 2; mt++)
#pragma unroll
                for (int nt = 0; nt < 4; nt++)
                    mma_tf32(acc[mt][nt], a[mt], b[nt]);
        }
    }

#pragma unroll
    for (int mt = 0; mt < 2; mt++)
#pragma unroll
        for (int nt = 0; nt < 4; nt++) {
            int row = m0 + warp_m * 32 + mt * 16 + g;
            int col = warp_n * 32 + nt * 8 + c * 2;
            *(float2*)(Cout + (size_t)row * HID + col)       = make_float2(acc[mt][nt][0], acc[mt][nt][1]);
            *(float2*)(Cout + (size_t)(row + 8) * HID + col) = make_float2(acc[mt][nt][2], acc[mt][nt][3]);
        }
#undef G2_ISSUE
}

// ---------------- 6) combine ----------------
__global__ void __launch_bounds__(256) combine_kernel(float* __restrict__ out) {
    int s = blockIdx.x;
    int h = threadIdx.x * 4;
    int sl1 = g_slot1[s], sl2 = g_slot2[s];
    float w1 = g_fw1[s], w2 = g_fw2[s];
    float4 a = *(const float4*)(g_EOUT + (size_t)sl1 * HID + h);
    float4 b = *(const float4*)(g_EOUT + (size_t)sl2 * HID + h);
    float4 o;
    o.x = w1 * a.x + w2 * b.x;
    o.y = w1 * a.y + w2 * b.y;
    o.z = w1 * a.z + w2 * b.z;
    o.w = w1 * a.w + w2 * b.w;
    *(float4*)(out + (size_t)s * HID + h) = o;
}

// ---------------- launch ----------------
extern "C" void kernel_launch(void* const* d_in, const int* in_sizes, int n_in,
                              void* d_out, int out_size) {
    const float* hid = (const float*)d_in[0];
    const float* gw  = (const float*)d_in[1];
    const float* wg  = (const float*)d_in[2];
    const float* wu  = (const float*)d_in[3];
    const float* wd  = (const float*)d_in[4];
    float* out = (float*)d_out;

    cudaFuncSetAttribute(gemm1_kernel, cudaFuncAttributeMaxDynamicSharedMemorySize, G1_SMEM);
    cudaFuncSetAttribute(gemm2_kernel, cudaFuncAttributeMaxDynamicSharedMemorySize, G2_SMEM);

    router_kernel<<<S_TOK, 256>>>(hid, gw);
    scan_kernel<<<1, 256>>>();
    gemm1_kernel<<<dim3(10, 64, 8), 512, G1_SMEM>>>(hid, wg, wu);
    gemm2_kernel<<<dim3(10, 8, 8), 512, G2_SMEM>>>(wd);
    combine_kernel<<<S_TOK, 256>>>(out);
}